// round 13
// baseline (speedup 1.0000x reference)
#include <cuda_runtime.h>
#include <cuda_bf16.h>
#include <cstdint>

typedef unsigned long long ull;

// ---------------- scratch (device globals; no allocation allowed) ----------------
__device__ float g_pooled[512 * 90];
__device__ float g_X[512 * 4096];
__device__ float g_Ypart[32 * 512 * 128];   // split-K partials for fc7||fcast
__device__ float g_A1[512 * 256];           // Wih1@emb + bih1 + bhh1
__device__ float g_AF1[512 * 256];          // Wih1@fcast + bih1 + bhh1
__device__ float2 g_hc1[512 * 64];          // (h1, c1) per step
__device__ float2 g_hc2[512 * 32];          // (h2, c2) per step
// transposed weights [k][r] for coalesced matvec reads
__device__ float g_WT1[64 * 256];    // Whh1^T
__device__ float g_WTih1[64 * 256];  // Wih1^T
__device__ float g_WTI2[64 * 128];   // Wih2^T
__device__ float g_WTH2[32 * 128];   // Whh2^T

// ---------------- helpers ----------------
__device__ __forceinline__ unsigned enc_f(float f) {
    unsigned u = __float_as_uint(f);
    return (u & 0x80000000u) ? ~u : (u | 0x80000000u);
}
__device__ __forceinline__ float dec_f(unsigned k) {
    return __uint_as_float((k & 0x80000000u) ? (k ^ 0x80000000u) : ~k);
}
// hardware tanh (MUFU.TANH, ~16cy)
__device__ __forceinline__ float tanha(float x) {
    float y;
    asm("tanh.approx.f32 %0, %1;" : "=f"(y) : "f"(x));
    return y;
}
__device__ __forceinline__ float sigf(float x) {
    return fmaf(tanha(0.5f * x), 0.5f, 0.5f);   // sigmoid(x) = 0.5*(1+tanh(x/2))
}
// packed f32x2 ops (FFMA2 path — only reachable via PTX)
__device__ __forceinline__ ull fma2(ull a, ull b, ull c) {
    ull d;
    asm("fma.rn.f32x2 %0, %1, %2, %3;" : "=l"(d) : "l"(a), "l"(b), "l"(c));
    return d;
}
__device__ __forceinline__ ull add2(ull a, ull b) {
    ull d;
    asm("add.rn.f32x2 %0, %1, %2;" : "=l"(d) : "l"(a), "l"(b));
    return d;
}
__device__ __forceinline__ ull pack2(float lo, float hi) {
    ull d;
    asm("mov.b64 %0, {%1, %2};" : "=l"(d) : "f"(lo), "f"(hi));
    return d;
}
__device__ __forceinline__ float hsum2(ull a) {
    float x, y;
    asm("mov.b64 {%0, %1}, %2;" : "=f"(x), "=f"(y) : "l"(a));
    return x + y;
}

// ---------------- K1: SPP pooling, per-128-step chunk (+ folded transpose in chunk 0) ----
// grid 384 (= 128 steps * 3 channels), block 256
__global__ void spp_kernel(const float* __restrict__ frames, float* __restrict__ pooled,
                           int s_base,
                           const float* __restrict__ Whh1, const float* __restrict__ Wih1,
                           const float* __restrict__ Wih2, const float* __restrict__ Whh2) {
    __shared__ unsigned cm[144];   // 12x12 grid of 16x16-block maxes, encoded
    int tid = threadIdx.x;
    int b = blockIdx.x;

    // folded transpose: first 64 CTAs of chunk 0 emit the [k][r] weight copies
    if (s_base == 0 && b < 64) {
        int t = b * 256 + tid;
        {
            int r = t >> 6, k = t & 63;
            g_WT1[k * 256 + r] = Whh1[t];
            g_WTih1[k * 256 + r] = Wih1[t];
        }
        if (t < 8192) {
            int r = t >> 6, k = t & 63;
            g_WTI2[k * 128 + r] = Wih2[t];
        }
        if (t < 4096) {
            int r = t >> 5, k = t & 31;
            g_WTH2[k * 128 + r] = Whh2[t];
        }
    }

    int sl = b / 3;
    int c = b - sl * 3;
    int s = s_base + sl;
    if (tid < 144) cm[tid] = 0u;
    __syncthreads();

    const float4* base = reinterpret_cast<const float4*>(frames + ((size_t)s * 3 + c) * 36864);
    for (int seg = tid; seg < 2304; seg += 256) {
        const float4* p = base + seg * 4;
        float4 a = p[0], b4 = p[1], c4 = p[2], d4 = p[3];
        float m = fmaxf(fmaxf(fmaxf(a.x, a.y), fmaxf(a.z, a.w)),
                        fmaxf(fmaxf(b4.x, b4.y), fmaxf(b4.z, b4.w)));
        m = fmaxf(m, fmaxf(fmaxf(c4.x, c4.y), fmaxf(c4.z, c4.w)));
        m = fmaxf(m, fmaxf(fmaxf(d4.x, d4.y), fmaxf(d4.z, d4.w)));
        int row = seg / 12;
        int wc = seg - row * 12;
        int cell = (row >> 4) * 12 + wc;
        atomicMax(&cm[cell], enc_f(m));
    }
    __syncthreads();

    if (tid < 30) {
        unsigned m = 0u;
        int off;
        if (tid < 16) {
            int i = tid >> 2, j = tid & 3;
            for (int r = 3 * i; r < 3 * i + 3; r++)
                for (int q = 3 * j; q < 3 * j + 3; q++)
                    m = max(m, cm[r * 12 + q]);
            off = c * 16 + tid;
        } else if (tid < 25) {
            int t2 = tid - 16, i = t2 / 3, j = t2 - 3 * (t2 / 3);
            for (int r = 4 * i; r < 4 * i + 4; r++)
                for (int q = 4 * j; q < 4 * j + 4; q++)
                    m = max(m, cm[r * 12 + q]);
            off = 48 + c * 9 + t2;
        } else if (tid < 29) {
            int t2 = tid - 25, i = t2 >> 1, j = t2 & 1;
            for (int r = 6 * i; r < 6 * i + 6; r++)
                for (int q = 6 * j; q < 6 * j + 6; q++)
                    m = max(m, cm[r * 12 + q]);
            off = 75 + c * 4 + t2;
        } else {
            for (int r = 0; r < 144; r++) m = max(m, cm[r]);
            off = 87 + c;
        }
        pooled[s * 90 + off] = dec_f(m);
    }
}

// ---------------- K2: X = relu(pooled @ W_spp^T + b_spp), per-chunk ----------------
// grid (64, 4), block 256
__global__ void gemm1_kernel(const float* __restrict__ pooled,
                             const float* __restrict__ Wspp,
                             const float* __restrict__ bspp,
                             float* __restrict__ X, int s_base) {
    __shared__ float Ps[90][32];
    __shared__ float Ws[90][64];
    int tid = threadIdx.x;
    int e0 = blockIdx.x * 64;
    int s0 = s_base + blockIdx.y * 32;

    for (int idx = tid; idx < 2880; idx += 256) {
        int k = idx >> 5, si = idx & 31;
        Ps[k][si] = pooled[(s0 + si) * 90 + k];
    }
    for (int idx = tid; idx < 5760; idx += 256) {
        int k = idx >> 6, e = idx & 63;
        Ws[k][e] = Wspp[(size_t)(e0 + e) * 90 + k];
    }
    __syncthreads();

    int ex = tid & 63, sg = tid >> 6;
    float acc[8];
#pragma unroll
    for (int j = 0; j < 8; j++) acc[j] = 0.f;
    for (int k = 0; k < 90; k++) {
        float w = Ws[k][ex];
#pragma unroll
        for (int j = 0; j < 8; j++) acc[j] += w * Ps[k][sg * 8 + j];
    }
    float bias = bspp[e0 + ex];
#pragma unroll
    for (int j = 0; j < 8; j++) {
        int s = s0 + sg * 8 + j;
        X[(size_t)s * 4096 + e0 + ex] = fmaxf(acc[j] + bias, 0.f);
    }
}

// ---------------- K3: split-K GEMM, per-chunk, FFMA2 + reg-staged double buffering ------
// grid (32 k-splits, 2 s-tiles), block 256
__global__ void gemm2_kernel(const float* __restrict__ X,
                             const float* __restrict__ Wfc7,
                             const float* __restrict__ Wfcast,
                             float* __restrict__ Ypart, int s_base) {
    __shared__ float Xs[2][64][36];
    __shared__ float Ws2[2][32][128];
    int tid = threadIdx.x;
    int ks = blockIdx.x;
    int s0 = s_base + blockIdx.y * 64;
    int k0 = ks * 128;
    int tx = tid & 15, ty = tid >> 4;

    ull acc[4][4];
#pragma unroll
    for (int j = 0; j < 4; j++)
#pragma unroll
        for (int u = 0; u < 4; u++) acc[j][u] = 0ull;

    float4 xr[2], wr[4];
    auto ldg_chunk = [&](int kc) {
#pragma unroll
        for (int m = 0; m < 2; m++) {
            int idx = tid + 256 * m;
            int si = idx >> 3, kv = idx & 7;
            xr[m] = *reinterpret_cast<const float4*>(
                &X[(size_t)(s0 + si) * 4096 + k0 + kc + kv * 4]);
        }
#pragma unroll
        for (int m = 0; m < 4; m++) {
            int idx = tid + 256 * m;
            int e = idx >> 3, kv = idx & 7;
            const float* wrow = (e < 64) ? (Wfc7 + (size_t)e * 4096)
                                         : (Wfcast + (size_t)(e - 64) * 4096);
            wr[m] = *reinterpret_cast<const float4*>(&wrow[k0 + kc + kv * 4]);
        }
    };
    auto sts_chunk = [&](int buf) {
#pragma unroll
        for (int m = 0; m < 2; m++) {
            int idx = tid + 256 * m;
            int si = idx >> 3, kv = idx & 7;
            *reinterpret_cast<float4*>(&Xs[buf][si][kv * 4]) = xr[m];
        }
#pragma unroll
        for (int m = 0; m < 4; m++) {
            int idx = tid + 256 * m;
            int e = idx >> 3, kv = idx & 7;
            Ws2[buf][kv * 4 + 0][e] = wr[m].x;
            Ws2[buf][kv * 4 + 1][e] = wr[m].y;
            Ws2[buf][kv * 4 + 2][e] = wr[m].z;
            Ws2[buf][kv * 4 + 3][e] = wr[m].w;
        }
    };

    ldg_chunk(0);
    sts_chunk(0);

    for (int c = 0; c < 4; c++) {
        __syncthreads();
        if (c < 3) ldg_chunk((c + 1) * 32);
        int buf = c & 1;
#pragma unroll 4
        for (int k = 0; k < 32; k++) {
            ull xp[4];
#pragma unroll
            for (int j = 0; j < 4; j++) {
                float xa = Xs[buf][ty * 4 + j][k];
                xp[j] = pack2(xa, xa);
            }
            const ulonglong2* wrow =
                reinterpret_cast<const ulonglong2*>(&Ws2[buf][k][tx * 8]);
            ulonglong2 w01 = wrow[0];
            ulonglong2 w23 = wrow[1];
#pragma unroll
            for (int j = 0; j < 4; j++) {
                acc[j][0] = fma2(xp[j], w01.x, acc[j][0]);
                acc[j][1] = fma2(xp[j], w01.y, acc[j][1]);
                acc[j][2] = fma2(xp[j], w23.x, acc[j][2]);
                acc[j][3] = fma2(xp[j], w23.y, acc[j][3]);
            }
        }
        if (c < 3) sts_chunk((c + 1) & 1);
    }

    ull* Yp = reinterpret_cast<ull*>(Ypart);
#pragma unroll
    for (int j = 0; j < 4; j++) {
        int s = s0 + ty * 4 + j;
#pragma unroll
        for (int u = 0; u < 4; u++)
            Yp[((size_t)ks * 512 + s) * 64 + tx * 4 + u] = acc[j][u];
    }
}

// ---------------- K4: reduce partials (split across halves), relu, project ----------
// grid 128, block 256
__global__ void __launch_bounds__(256)
proj_kernel(const float* __restrict__ Ypart,
            const float* __restrict__ bfc7,
            const float* __restrict__ bfcast,
            const float* __restrict__ bih1,
            const float* __restrict__ bhh1,
            float* __restrict__ A1, float* __restrict__ AF1, int s_base) {
    __shared__ float red[2][128];
    __shared__ float xe[64], xf[64];
    int tid = threadIdx.x;
    int s = s_base + blockIdx.x;

    // phase 1: 256 threads, each reduces 16 of the 32 partials for one column
    {
        int half = tid >> 7, col = tid & 127;
        int pb = half * 16;
        float a0 = 0.f, a1 = 0.f, a2 = 0.f, a3 = 0.f;
#pragma unroll
        for (int p = 0; p < 16; p += 4) {
            a0 += Ypart[((size_t)(pb + p) * 512 + s) * 128 + col];
            a1 += Ypart[((size_t)(pb + p + 1) * 512 + s) * 128 + col];
            a2 += Ypart[((size_t)(pb + p + 2) * 512 + s) * 128 + col];
            a3 += Ypart[((size_t)(pb + p + 3) * 512 + s) * 128 + col];
        }
        red[half][col] = (a0 + a1) + (a2 + a3);
    }
    __syncthreads();
    if (tid < 128) {
        float a = red[0][tid] + red[1][tid]
                + ((tid < 64) ? bfc7[tid] : bfcast[tid - 64]);
        a = fmaxf(a, 0.f);
        if (tid < 64) xe[tid] = a; else xf[tid - 64] = a;
    }
    __syncthreads();

    // phase 2: project through Wih1^T (coalesced)
    int r = tid;
    float a = bih1[r] + bhh1[r];
    float af = a;
#pragma unroll 8
    for (int k = 0; k < 64; k++) {
        float w = g_WTih1[k * 256 + r];
        a += w * xe[k];
        af += w * xf[k];
    }
    A1[s * 256 + r] = a;
    AF1[s * 256 + r] = af;
}

// ---------------- K5: scan chunk (128 steps); state carried through g_hc1/g_hc2 ---------
#define BAR256() asm volatile("bar.sync 0, 256;" ::: "memory")

__global__ void __launch_bounds__(256, 1)
lstm_chunk_kernel(const float* __restrict__ Whh1,
                  const float* __restrict__ Wih2,
                  const float* __restrict__ Whh2,
                  const float* __restrict__ bih2,
                  const float* __restrict__ bhh2,
                  int chunk) {
    __shared__ __align__(16) float h1buf[2][64];
    __shared__ __align__(16) float h2buf[2][32];

    int t = threadIdx.x;
    int i0 = chunk * 128;   // always even -> prev state lives in ring slot 1
    if (t < 64) {
        float2 prev = chunk ? g_hc1[(i0 - 1) * 64 + t] : make_float2(0.f, 0.f);
        h1buf[1][t] = prev.x;
        h1buf[0][t] = 0.f;
    }
    if (t >= 64 && t < 96) {
        float2 prev = chunk ? g_hc2[(i0 - 1) * 32 + (t - 64)] : make_float2(0.f, 0.f);
        h2buf[1][t - 64] = prev.x;
        h2buf[0][t - 64] = 0.f;
    }

    if (t < 128) {
        // ---- L1: cell1; 2 rows/thread of Whh1, packed f32x2 ----
        int p = t >> 1;
        int odd = t & 1;
        int rA = odd ? (64 + p) : p;          // f_p : i_p
        int rB = odd ? (192 + p) : (128 + p); // o_p : g_p
        ull wA[32], wB[32];
        const ull* WA = reinterpret_cast<const ull*>(Whh1 + (size_t)rA * 64);
        const ull* WB = reinterpret_cast<const ull*>(Whh1 + (size_t)rB * 64);
#pragma unroll
        for (int k = 0; k < 32; k++) { wA[k] = WA[k]; wB[k] = WB[k]; }
        float c1 = (!odd && chunk) ? g_hc1[(i0 - 1) * 64 + p].y : 0.f;
        float a1A0 = g_A1[i0 * 256 + rA],         a1B0 = g_A1[i0 * 256 + rB];
        float a1A1 = g_A1[(i0 + 1) * 256 + rA],   a1B1 = g_A1[(i0 + 1) * 256 + rB];
        BAR256();

        for (int m = 0; m < 129; m++) {
            if (m < 128) {
                int i = i0 + m;
                int rd = (i & 1) ^ 1, wr = i & 1;
                const ulonglong2* hv = reinterpret_cast<const ulonglong2*>(h1buf[rd]);
                ull sA0 = 0ull, sA1 = 0ull, sA2 = 0ull, sA3 = 0ull;
                ull sB0 = 0ull, sB1 = 0ull, sB2 = 0ull, sB3 = 0ull;
#pragma unroll
                for (int k = 0; k < 16; k += 2) {
                    ulonglong2 h0 = hv[k];
                    ulonglong2 h1 = hv[k + 1];
                    sA0 = fma2(wA[2 * k], h0.x, sA0);     sA1 = fma2(wA[2 * k + 1], h0.y, sA1);
                    sB0 = fma2(wB[2 * k], h0.x, sB0);     sB1 = fma2(wB[2 * k + 1], h0.y, sB1);
                    sA2 = fma2(wA[2 * k + 2], h1.x, sA2); sA3 = fma2(wA[2 * k + 3], h1.y, sA3);
                    sB2 = fma2(wB[2 * k + 2], h1.x, sB2); sB3 = fma2(wB[2 * k + 3], h1.y, sB3);
                }
                float own0 = hsum2(add2(add2(sA0, sA1), add2(sA2, sA3))) + a1A0;
                float own1 = hsum2(add2(add2(sB0, sB1), add2(sB2, sB3))) + a1B0;
                a1A0 = a1A1; a1B0 = a1B1;
                if (m + 2 < 128) {
                    a1A1 = __ldg(&g_A1[(i + 2) * 256 + rA]);
                    a1B1 = __ldg(&g_A1[(i + 2) * 256 + rB]);
                }
                // activate first (parallel across pair), then exchange activated values
                float act0 = sigf(own0);                          // even: iv, odd: fv
                float act1 = odd ? sigf(own1) : tanha(own1);      // even: gv, odd: ov
                float x0 = __shfl_xor_sync(0xffffffffu, act0, 1); // even <- fv
                float x1 = __shfl_xor_sync(0xffffffffu, act1, 1); // even <- ov
                if (!odd) {
                    c1 = x0 * c1 + act0 * act1;
                    float h1n = x1 * tanha(c1);
                    h1buf[wr][p] = h1n;
                    g_hc1[i * 64 + p] = make_float2(h1n, c1);
                }
            }
            BAR256();
        }
    } else {
        // ---- L2: cell2, one step behind; 1 row/thread, packed f32x2 ----
        int u = t - 128;
        int v = u >> 2;   // element 0..31
        int q = u & 3;    // gate 0..3 (i,f,g,o)
        int lb = (u & 31) & ~3;   // base lane of this thread's quad
        int r2 = q * 32 + v;
        ull wI[32], wH[16];
        const ull* WI = reinterpret_cast<const ull*>(Wih2 + (size_t)r2 * 64);
        const ull* WH = reinterpret_cast<const ull*>(Whh2 + (size_t)r2 * 32);
#pragma unroll
        for (int k = 0; k < 32; k++) wI[k] = WI[k];
#pragma unroll
        for (int k = 0; k < 16; k++) wH[k] = WH[k];
        float b2 = bih2[r2] + bhh2[r2];
        float c2 = (q == 0 && chunk) ? g_hc2[(i0 - 1) * 32 + v].y : 0.f;
        BAR256();

        for (int m = 0; m < 129; m++) {
            if (m >= 1) {
                int j = i0 + m - 1;   // cell2(j): needs h1(j), h2(j-1)
                const ulonglong2* h1v = reinterpret_cast<const ulonglong2*>(h1buf[j & 1]);
                const ulonglong2* h2v = reinterpret_cast<const ulonglong2*>(h2buf[(j + 1) & 1]);
                ull s0 = 0ull, s1 = 0ull, s2 = 0ull, s3 = 0ull;
#pragma unroll
                for (int k = 0; k < 8; k += 2) {
                    ulonglong2 h0 = h2v[k];
                    ulonglong2 h1 = h2v[k + 1];
                    s0 = fma2(wH[2 * k], h0.x, s0);     s1 = fma2(wH[2 * k + 1], h0.y, s1);
                    s2 = fma2(wH[2 * k + 2], h1.x, s2); s3 = fma2(wH[2 * k + 3], h1.y, s3);
                }
#pragma unroll
                for (int k = 0; k < 16; k += 2) {
                    ulonglong2 h0 = h1v[k];
                    ulonglong2 h1 = h1v[k + 1];
                    s0 = fma2(wI[2 * k], h0.x, s0);     s1 = fma2(wI[2 * k + 1], h0.y, s1);
                    s2 = fma2(wI[2 * k + 2], h1.x, s2); s3 = fma2(wI[2 * k + 3], h1.y, s3);
                }
                float g2 = hsum2(add2(add2(s0, s1), add2(s2, s3))) + b2;
                // activate first: q=2 (g) -> tanh; i,f,o -> sigmoid
                float act = (q == 2) ? tanha(g2) : sigf(g2);
                // three INDEPENDENT index shuffles (no dependent hop)
                float fv = __shfl_sync(0xffffffffu, act, lb | 1, 32);
                float gv = __shfl_sync(0xffffffffu, act, lb | 2, 32);
                float ov = __shfl_sync(0xffffffffu, act, lb | 3, 32);
                if (q == 0) {
                    c2 = fv * c2 + act * gv;          // act = iv
                    float h2n = ov * tanha(c2);
                    h2buf[j & 1][v] = h2n;
                    g_hc2[j * 32 + v] = make_float2(h2n, c2);
                }
            }
            BAR256();
        }
    }
}

// ---------------- K6: batched forecast cells + both output heads ----------------
// grid 512 (one per step), block 256
__global__ void post_kernel(const float* __restrict__ bih2,
                            const float* __restrict__ bhh2,
                            const float* __restrict__ Wfc8,
                            const float* __restrict__ bfc8,
                            float* __restrict__ out) {
    __shared__ float sh1[64], sh2[32], sfh1[64];
    __shared__ float sg[256], sg2[128];
    int t = threadIdx.x;
    int s = blockIdx.x;
    float c1v = 0.f, c2v = 0.f;
    if (t < 64) {
        float2 v = g_hc1[s * 64 + t];
        sh1[t] = v.x;
        c1v = v.y;
    }
    if (t < 32) {
        float2 v = g_hc2[s * 32 + t];
        sh2[t] = v.x;
        c2v = v.y;
    }
    __syncthreads();

    {
        float a = g_AF1[s * 256 + t];
#pragma unroll 8
        for (int k = 0; k < 64; k++)
            a += g_WT1[k * 256 + t] * sh1[k];
        sg[t] = a;
    }
    __syncthreads();
    if (t < 64) {
        float iv = sigf(sg[t]), fv = sigf(sg[64 + t]);
        float gv = tanha(sg[128 + t]), ov = sigf(sg[192 + t]);
        float cf = fv * c1v + iv * gv;
        sfh1[t] = ov * tanha(cf);
    }
    __syncthreads();

    if (t < 128) {
        float a = bih2[t] + bhh2[t];
#pragma unroll 8
        for (int k = 0; k < 64; k++)
            a += g_WTI2[k * 128 + t] * sfh1[k];
#pragma unroll 8
        for (int k = 0; k < 32; k++)
            a += g_WTH2[k * 128 + t] * sh2[k];
        sg2[t] = a;
    }
    __syncthreads();
    if (t < 32) {
        float iv = sigf(sg2[t]), fv = sigf(sg2[32 + t]);
        float gv = tanha(sg2[64 + t]), ov = sigf(sg2[96 + t]);
        float cf = fv * c2v + iv * gv;
        float fh2 = ov * tanha(cf);
        float w = Wfc8[t];
        float pd = w * sh2[t];
        float fd = w * fh2;
#pragma unroll
        for (int o = 16; o; o >>= 1) {
            pd += __shfl_down_sync(0xffffffffu, pd, o);
            fd += __shfl_down_sync(0xffffffffu, fd, o);
        }
        if (t == 0) {
            float b8 = bfc8[0];
            out[s] = sigf(pd + b8);
            out[512 + s] = sigf(fd + b8);
        }
    }
}

// ---------------- launch: R11 topology (2 streams, event edges, single post) -----------
extern "C" void kernel_launch(void* const* d_in, const int* in_sizes, int n_in,
                              void* d_out, int out_size) {
    const float* frames = (const float*)d_in[0];
    const float* W_spp  = (const float*)d_in[1];
    const float* b_spp  = (const float*)d_in[2];
    const float* W_fc7  = (const float*)d_in[3];
    const float* b_fc7  = (const float*)d_in[4];
    const float* W_fcast= (const float*)d_in[5];
    const float* b_fcast= (const float*)d_in[6];
    const float* Wih1   = (const float*)d_in[7];
    const float* Whh1   = (const float*)d_in[8];
    const float* bih1   = (const float*)d_in[9];
    const float* bhh1   = (const float*)d_in[10];
    const float* Wih2   = (const float*)d_in[11];
    const float* Whh2   = (const float*)d_in[12];
    const float* bih2   = (const float*)d_in[13];
    const float* bhh2   = (const float*)d_in[14];
    const float* W_fc8  = (const float*)d_in[15];
    const float* b_fc8  = (const float*)d_in[16];
    float* out = (float*)d_out;

    float *p_pooled, *p_X, *p_Ypart, *p_A1, *p_AF1;
    cudaGetSymbolAddress((void**)&p_pooled, g_pooled);
    cudaGetSymbolAddress((void**)&p_X, g_X);
    cudaGetSymbolAddress((void**)&p_Ypart, g_Ypart);
    cudaGetSymbolAddress((void**)&p_A1, g_A1);
    cudaGetSymbolAddress((void**)&p_AF1, g_AF1);

    // one-time handle creation (reused on every call — identical work each launch,
    // and the capture call performs no new host/driver allocations)
    static cudaStream_t s2 = nullptr;
    static cudaEvent_t evP[4], evL;
    if (!s2) {
        cudaStreamCreateWithFlags(&s2, cudaStreamNonBlocking);
        for (int c = 0; c < 4; c++)
            cudaEventCreateWithFlags(&evP[c], cudaEventDisableTiming);
        cudaEventCreateWithFlags(&evL, cudaEventDisableTiming);
    }

    for (int c = 0; c < 4; c++) {
        int sb = c * 128;
        // production chunk on the main (capturing) stream
        spp_kernel<<<384, 256>>>(frames, p_pooled, sb, Whh1, Wih1, Wih2, Whh2);
        gemm1_kernel<<<dim3(64, 4), 256>>>(p_pooled, W_spp, b_spp, p_X, sb);
        gemm2_kernel<<<dim3(32, 2), 256>>>(p_X, W_fc7, W_fcast, p_Ypart, sb);
        proj_kernel<<<128, 256>>>(p_Ypart, b_fc7, b_fcast, bih1, bhh1, p_A1, p_AF1, sb);
        cudaEventRecord(evP[c], 0);
        // scan chunk on the forked stream, gated by the production chunk's event
        cudaStreamWaitEvent(s2, evP[c], 0);
        lstm_chunk_kernel<<<1, 256, 0, s2>>>(Whh1, Wih2, Whh2, bih2, bhh2, c);
    }

    // join and finish
    cudaEventRecord(evL, s2);
    cudaStreamWaitEvent(0, evL, 0);
    post_kernel<<<512, 256>>>(bih2, bhh2, W_fc8, b_fc8, out);
}

// round 14
// speedup vs baseline: 1.0399x; 1.0399x over previous
#include <cuda_runtime.h>
#include <cuda_bf16.h>
#include <cstdint>

typedef unsigned long long ull;

// ---------------- scratch (device globals; no allocation allowed) ----------------
__device__ float g_pooled[512 * 90];
__device__ float g_X[512 * 4096];
__device__ float g_Ypart[32 * 512 * 128];   // split-K partials for fc7||fcast
__device__ float g_A1[512 * 256];           // Wih1@emb + bih1 + bhh1
__device__ float g_AF1[512 * 256];          // Wih1@fcast + bih1 + bhh1
__device__ float g_G2pre[512 * 128];        // Wih2@h1 + bih2 + bhh2 per step
__device__ float2 g_hc1[512 * 64];          // (h1, c1) per step
__device__ float2 g_hc2[512 * 32];          // (h2, c2) per step
// transposed weights [k][r] for coalesced matvec reads
__device__ float g_WT1[64 * 256];    // Whh1^T
__device__ float g_WTih1[64 * 256];  // Wih1^T
__device__ float g_WTI2[64 * 128];   // Wih2^T
__device__ float g_WTH2[32 * 128];   // Whh2^T

// ---------------- helpers ----------------
__device__ __forceinline__ unsigned enc_f(float f) {
    unsigned u = __float_as_uint(f);
    return (u & 0x80000000u) ? ~u : (u | 0x80000000u);
}
__device__ __forceinline__ float dec_f(unsigned k) {
    return __uint_as_float((k & 0x80000000u) ? (k ^ 0x80000000u) : ~k);
}
// hardware tanh (MUFU.TANH, ~16cy)
__device__ __forceinline__ float tanha(float x) {
    float y;
    asm("tanh.approx.f32 %0, %1;" : "=f"(y) : "f"(x));
    return y;
}
__device__ __forceinline__ float sigf(float x) {
    return fmaf(tanha(0.5f * x), 0.5f, 0.5f);   // sigmoid(x) = 0.5*(1+tanh(x/2))
}
// packed f32x2 ops (FFMA2 path — only reachable via PTX)
__device__ __forceinline__ ull fma2(ull a, ull b, ull c) {
    ull d;
    asm("fma.rn.f32x2 %0, %1, %2, %3;" : "=l"(d) : "l"(a), "l"(b), "l"(c));
    return d;
}
__device__ __forceinline__ ull add2(ull a, ull b) {
    ull d;
    asm("add.rn.f32x2 %0, %1, %2;" : "=l"(d) : "l"(a), "l"(b));
    return d;
}
__device__ __forceinline__ ull pack2(float lo, float hi) {
    ull d;
    asm("mov.b64 %0, {%1, %2};" : "=l"(d) : "f"(lo), "f"(hi));
    return d;
}
__device__ __forceinline__ float hsum2(ull a) {
    float x, y;
    asm("mov.b64 {%0, %1}, %2;" : "=f"(x), "=f"(y) : "l"(a));
    return x + y;
}

// ---------------- K1: SPP pooling, per-128-step chunk (+ folded transpose in chunk 0) ----
// grid 384, block 256
__global__ void spp_kernel(const float* __restrict__ frames, float* __restrict__ pooled,
                           int s_base,
                           const float* __restrict__ Whh1, const float* __restrict__ Wih1,
                           const float* __restrict__ Wih2, const float* __restrict__ Whh2) {
    __shared__ unsigned cm[144];
    int tid = threadIdx.x;
    int b = blockIdx.x;

    if (s_base == 0 && b < 64) {
        int t = b * 256 + tid;
        {
            int r = t >> 6, k = t & 63;
            g_WT1[k * 256 + r] = Whh1[t];
            g_WTih1[k * 256 + r] = Wih1[t];
        }
        if (t < 8192) {
            int r = t >> 6, k = t & 63;
            g_WTI2[k * 128 + r] = Wih2[t];
        }
        if (t < 4096) {
            int r = t >> 5, k = t & 31;
            g_WTH2[k * 128 + r] = Whh2[t];
        }
    }

    int sl = b / 3;
    int c = b - sl * 3;
    int s = s_base + sl;
    if (tid < 144) cm[tid] = 0u;
    __syncthreads();

    const float4* base = reinterpret_cast<const float4*>(frames + ((size_t)s * 3 + c) * 36864);
    for (int seg = tid; seg < 2304; seg += 256) {
        const float4* p = base + seg * 4;
        float4 a = p[0], b4 = p[1], c4 = p[2], d4 = p[3];
        float m = fmaxf(fmaxf(fmaxf(a.x, a.y), fmaxf(a.z, a.w)),
                        fmaxf(fmaxf(b4.x, b4.y), fmaxf(b4.z, b4.w)));
        m = fmaxf(m, fmaxf(fmaxf(c4.x, c4.y), fmaxf(c4.z, c4.w)));
        m = fmaxf(m, fmaxf(fmaxf(d4.x, d4.y), fmaxf(d4.z, d4.w)));
        int row = seg / 12;
        int wc = seg - row * 12;
        int cell = (row >> 4) * 12 + wc;
        atomicMax(&cm[cell], enc_f(m));
    }
    __syncthreads();

    if (tid < 30) {
        unsigned m = 0u;
        int off;
        if (tid < 16) {
            int i = tid >> 2, j = tid & 3;
            for (int r = 3 * i; r < 3 * i + 3; r++)
                for (int q = 3 * j; q < 3 * j + 3; q++)
                    m = max(m, cm[r * 12 + q]);
            off = c * 16 + tid;
        } else if (tid < 25) {
            int t2 = tid - 16, i = t2 / 3, j = t2 - 3 * (t2 / 3);
            for (int r = 4 * i; r < 4 * i + 4; r++)
                for (int q = 4 * j; q < 4 * j + 4; q++)
                    m = max(m, cm[r * 12 + q]);
            off = 48 + c * 9 + t2;
        } else if (tid < 29) {
            int t2 = tid - 25, i = t2 >> 1, j = t2 & 1;
            for (int r = 6 * i; r < 6 * i + 6; r++)
                for (int q = 6 * j; q < 6 * j + 6; q++)
                    m = max(m, cm[r * 12 + q]);
            off = 75 + c * 4 + t2;
        } else {
            for (int r = 0; r < 144; r++) m = max(m, cm[r]);
            off = 87 + c;
        }
        pooled[s * 90 + off] = dec_f(m);
    }
}

// ---------------- K2: X = relu(pooled @ W_spp^T + b_spp), per-chunk ----------------
// grid (64, 4), block 256
__global__ void gemm1_kernel(const float* __restrict__ pooled,
                             const float* __restrict__ Wspp,
                             const float* __restrict__ bspp,
                             float* __restrict__ X, int s_base) {
    __shared__ float Ps[90][32];
    __shared__ float Ws[90][64];
    int tid = threadIdx.x;
    int e0 = blockIdx.x * 64;
    int s0 = s_base + blockIdx.y * 32;

    for (int idx = tid; idx < 2880; idx += 256) {
        int k = idx >> 5, si = idx & 31;
        Ps[k][si] = pooled[(s0 + si) * 90 + k];
    }
    for (int idx = tid; idx < 5760; idx += 256) {
        int k = idx >> 6, e = idx & 63;
        Ws[k][e] = Wspp[(size_t)(e0 + e) * 90 + k];
    }
    __syncthreads();

    int ex = tid & 63, sg = tid >> 6;
    float acc[8];
#pragma unroll
    for (int j = 0; j < 8; j++) acc[j] = 0.f;
    for (int k = 0; k < 90; k++) {
        float w = Ws[k][ex];
#pragma unroll
        for (int j = 0; j < 8; j++) acc[j] += w * Ps[k][sg * 8 + j];
    }
    float bias = bspp[e0 + ex];
#pragma unroll
    for (int j = 0; j < 8; j++) {
        int s = s0 + sg * 8 + j;
        X[(size_t)s * 4096 + e0 + ex] = fmaxf(acc[j] + bias, 0.f);
    }
}

// ---------------- K3: split-K GEMM, per-chunk, FFMA2 + reg-staged double buffering ------
// grid (32, 2), block 256
__global__ void gemm2_kernel(const float* __restrict__ X,
                             const float* __restrict__ Wfc7,
                             const float* __restrict__ Wfcast,
                             float* __restrict__ Ypart, int s_base) {
    __shared__ float Xs[2][64][36];
    __shared__ float Ws2[2][32][128];
    int tid = threadIdx.x;
    int ks = blockIdx.x;
    int s0 = s_base + blockIdx.y * 64;
    int k0 = ks * 128;
    int tx = tid & 15, ty = tid >> 4;

    ull acc[4][4];
#pragma unroll
    for (int j = 0; j < 4; j++)
#pragma unroll
        for (int u = 0; u < 4; u++) acc[j][u] = 0ull;

    float4 xr[2], wr[4];
    auto ldg_chunk = [&](int kc) {
#pragma unroll
        for (int m = 0; m < 2; m++) {
            int idx = tid + 256 * m;
            int si = idx >> 3, kv = idx & 7;
            xr[m] = *reinterpret_cast<const float4*>(
                &X[(size_t)(s0 + si) * 4096 + k0 + kc + kv * 4]);
        }
#pragma unroll
        for (int m = 0; m < 4; m++) {
            int idx = tid + 256 * m;
            int e = idx >> 3, kv = idx & 7;
            const float* wrow = (e < 64) ? (Wfc7 + (size_t)e * 4096)
                                         : (Wfcast + (size_t)(e - 64) * 4096);
            wr[m] = *reinterpret_cast<const float4*>(&wrow[k0 + kc + kv * 4]);
        }
    };
    auto sts_chunk = [&](int buf) {
#pragma unroll
        for (int m = 0; m < 2; m++) {
            int idx = tid + 256 * m;
            int si = idx >> 3, kv = idx & 7;
            *reinterpret_cast<float4*>(&Xs[buf][si][kv * 4]) = xr[m];
        }
#pragma unroll
        for (int m = 0; m < 4; m++) {
            int idx = tid + 256 * m;
            int e = idx >> 3, kv = idx & 7;
            Ws2[buf][kv * 4 + 0][e] = wr[m].x;
            Ws2[buf][kv * 4 + 1][e] = wr[m].y;
            Ws2[buf][kv * 4 + 2][e] = wr[m].z;
            Ws2[buf][kv * 4 + 3][e] = wr[m].w;
        }
    };

    ldg_chunk(0);
    sts_chunk(0);

    for (int c = 0; c < 4; c++) {
        __syncthreads();
        if (c < 3) ldg_chunk((c + 1) * 32);
        int buf = c & 1;
#pragma unroll 4
        for (int k = 0; k < 32; k++) {
            ull xp[4];
#pragma unroll
            for (int j = 0; j < 4; j++) {
                float xa = Xs[buf][ty * 4 + j][k];
                xp[j] = pack2(xa, xa);
            }
            const ulonglong2* wrow =
                reinterpret_cast<const ulonglong2*>(&Ws2[buf][k][tx * 8]);
            ulonglong2 w01 = wrow[0];
            ulonglong2 w23 = wrow[1];
#pragma unroll
            for (int j = 0; j < 4; j++) {
                acc[j][0] = fma2(xp[j], w01.x, acc[j][0]);
                acc[j][1] = fma2(xp[j], w01.y, acc[j][1]);
                acc[j][2] = fma2(xp[j], w23.x, acc[j][2]);
                acc[j][3] = fma2(xp[j], w23.y, acc[j][3]);
            }
        }
        if (c < 3) sts_chunk((c + 1) & 1);
    }

    ull* Yp = reinterpret_cast<ull*>(Ypart);
#pragma unroll
    for (int j = 0; j < 4; j++) {
        int s = s0 + ty * 4 + j;
#pragma unroll
        for (int u = 0; u < 4; u++)
            Yp[((size_t)ks * 512 + s) * 64 + tx * 4 + u] = acc[j][u];
    }
}

// ---------------- K4: reduce partials, relu, project through Wih1^T ----------------
// grid 128, block 256
__global__ void __launch_bounds__(256)
proj_kernel(const float* __restrict__ Ypart,
            const float* __restrict__ bfc7,
            const float* __restrict__ bfcast,
            const float* __restrict__ bih1,
            const float* __restrict__ bhh1,
            float* __restrict__ A1, float* __restrict__ AF1, int s_base) {
    __shared__ float red[2][128];
    __shared__ float xe[64], xf[64];
    int tid = threadIdx.x;
    int s = s_base + blockIdx.x;

    {
        int half = tid >> 7, col = tid & 127;
        int pb = half * 16;
        float a0 = 0.f, a1 = 0.f, a2 = 0.f, a3 = 0.f;
#pragma unroll
        for (int p = 0; p < 16; p += 4) {
            a0 += Ypart[((size_t)(pb + p) * 512 + s) * 128 + col];
            a1 += Ypart[((size_t)(pb + p + 1) * 512 + s) * 128 + col];
            a2 += Ypart[((size_t)(pb + p + 2) * 512 + s) * 128 + col];
            a3 += Ypart[((size_t)(pb + p + 3) * 512 + s) * 128 + col];
        }
        red[half][col] = (a0 + a1) + (a2 + a3);
    }
    __syncthreads();
    if (tid < 128) {
        float a = red[0][tid] + red[1][tid]
                + ((tid < 64) ? bfc7[tid] : bfcast[tid - 64]);
        a = fmaxf(a, 0.f);
        if (tid < 64) xe[tid] = a; else xf[tid - 64] = a;
    }
    __syncthreads();

    int r = tid;
    float a = bih1[r] + bhh1[r];
    float af = a;
#pragma unroll 8
    for (int k = 0; k < 64; k++) {
        float w = g_WTih1[k * 256 + r];
        a += w * xe[k];
        af += w * xf[k];
    }
    A1[s * 256 + r] = a;
    AF1[s * 256 + r] = af;
}

// ---------------- K5a: L1-only scan chunk (128 steps) — the lone sequential chain -------
// 128 threads; thread pair (even,odd) owns element p's (i,f)/(g,o) rows
__global__ void __launch_bounds__(128, 1)
l1scan_kernel(const float* __restrict__ Whh1, int chunk) {
    __shared__ __align__(16) float h1buf[2][64];
    int t = threadIdx.x;
    int i0 = chunk * 128;   // even -> prev h1 lives in ring slot 1
    if (t < 64) {
        h1buf[1][t] = chunk ? g_hc1[(i0 - 1) * 64 + t].x : 0.f;
        h1buf[0][t] = 0.f;
    }

    int p = t >> 1;
    int odd = t & 1;
    int rA = odd ? (64 + p) : p;          // f_p : i_p
    int rB = odd ? (192 + p) : (128 + p); // o_p : g_p
    ull wA[32], wB[32];
    const ull* WA = reinterpret_cast<const ull*>(Whh1 + (size_t)rA * 64);
    const ull* WB = reinterpret_cast<const ull*>(Whh1 + (size_t)rB * 64);
#pragma unroll
    for (int k = 0; k < 32; k++) { wA[k] = WA[k]; wB[k] = WB[k]; }
    float c1 = (!odd && chunk) ? g_hc1[(i0 - 1) * 64 + p].y : 0.f;
    float a1A0 = g_A1[i0 * 256 + rA],       a1B0 = g_A1[i0 * 256 + rB];
    float a1A1 = g_A1[(i0 + 1) * 256 + rA], a1B1 = g_A1[(i0 + 1) * 256 + rB];
    __syncthreads();

    for (int m = 0; m < 128; m++) {
        int i = i0 + m;
        int rd = (i & 1) ^ 1, wr = i & 1;
        const ulonglong2* hv = reinterpret_cast<const ulonglong2*>(h1buf[rd]);
        ull sA0 = 0ull, sA1 = 0ull, sA2 = 0ull, sA3 = 0ull;
        ull sB0 = 0ull, sB1 = 0ull, sB2 = 0ull, sB3 = 0ull;
#pragma unroll
        for (int k = 0; k < 16; k += 2) {
            ulonglong2 h0 = hv[k];
            ulonglong2 h1 = hv[k + 1];
            sA0 = fma2(wA[2 * k], h0.x, sA0);     sA1 = fma2(wA[2 * k + 1], h0.y, sA1);
            sB0 = fma2(wB[2 * k], h0.x, sB0);     sB1 = fma2(wB[2 * k + 1], h0.y, sB1);
            sA2 = fma2(wA[2 * k + 2], h1.x, sA2); sA3 = fma2(wA[2 * k + 3], h1.y, sA3);
            sB2 = fma2(wB[2 * k + 2], h1.x, sB2); sB3 = fma2(wB[2 * k + 3], h1.y, sB3);
        }
        float own0 = hsum2(add2(add2(sA0, sA1), add2(sA2, sA3))) + a1A0;
        float own1 = hsum2(add2(add2(sB0, sB1), add2(sB2, sB3))) + a1B0;
        a1A0 = a1A1; a1B0 = a1B1;
        if (m + 2 < 128) {
            a1A1 = __ldg(&g_A1[(i + 2) * 256 + rA]);
            a1B1 = __ldg(&g_A1[(i + 2) * 256 + rB]);
        }
        // activate first (parallel across pair), then exchange activated values
        float act0 = sigf(own0);                          // even: iv, odd: fv
        float act1 = odd ? sigf(own1) : tanha(own1);      // even: gv, odd: ov
        float x0 = __shfl_xor_sync(0xffffffffu, act0, 1); // even <- fv
        float x1 = __shfl_xor_sync(0xffffffffu, act1, 1); // even <- ov
        if (!odd) {
            c1 = x0 * c1 + act0 * act1;
            float h1n = x1 * tanha(c1);
            h1buf[wr][p] = h1n;
            g_hc1[i * 64 + p] = make_float2(h1n, c1);
        }
        __syncthreads();
    }
}

// ---------------- K5b: batched G2pre = Wih2@h1 + bih2 + bhh2 (parallel over steps) ------
// grid 128 (step in chunk), block 128
__global__ void proj2_kernel(const float* __restrict__ bih2,
                             const float* __restrict__ bhh2, int s_base) {
    __shared__ float sh1[64];
    int t = threadIdx.x;
    int s = s_base + blockIdx.x;
    if (t < 64) sh1[t] = g_hc1[s * 64 + t].x;
    __syncthreads();
    float a = bih2[t] + bhh2[t];
#pragma unroll 8
    for (int k = 0; k < 64; k++)
        a += g_WTI2[k * 128 + t] * sh1[k];
    g_G2pre[s * 128 + t] = a;
}

// ---------------- K5c: L2-only scan chunk (cell2; G2pre prefetched) ----------------
// 128 threads; thread u: element v=u>>2, gate q=u&3
__global__ void __launch_bounds__(128, 1)
l2scan_kernel(const float* __restrict__ Whh2, int chunk) {
    __shared__ __align__(16) float h2s[2][32];
    int t = threadIdx.x;
    int i0 = chunk * 128;
    if (t < 32) {
        h2s[1][t] = chunk ? g_hc2[(i0 - 1) * 32 + t].x : 0.f;
        h2s[0][t] = 0.f;
    }
    int v = t >> 2;
    int q = t & 3;
    int lb = (t & 31) & ~3;
    int r2 = q * 32 + v;
    ull wH[16];
    const ull* WH = reinterpret_cast<const ull*>(Whh2 + (size_t)r2 * 32);
#pragma unroll
    for (int k = 0; k < 16; k++) wH[k] = WH[k];
    float c2 = (q == 0 && chunk) ? g_hc2[(i0 - 1) * 32 + v].y : 0.f;
    float g00 = g_G2pre[i0 * 128 + r2];
    float g01 = g_G2pre[(i0 + 1) * 128 + r2];
    __syncthreads();

    for (int m = 0; m < 128; m++) {
        int j = i0 + m;
        const ulonglong2* h2v = reinterpret_cast<const ulonglong2*>(h2s[(j + 1) & 1]); // h2(j-1)
        ull s0 = 0ull, s1 = 0ull, s2 = 0ull, s3 = 0ull;
#pragma unroll
        for (int k = 0; k < 8; k += 2) {
            ulonglong2 h0 = h2v[k];
            ulonglong2 h1 = h2v[k + 1];
            s0 = fma2(wH[2 * k], h0.x, s0);     s1 = fma2(wH[2 * k + 1], h0.y, s1);
            s2 = fma2(wH[2 * k + 2], h1.x, s2); s3 = fma2(wH[2 * k + 3], h1.y, s3);
        }
        float g2 = hsum2(add2(add2(s0, s1), add2(s2, s3))) + g00;
        g00 = g01;
        if (m + 2 < 128) g01 = __ldg(&g_G2pre[(j + 2) * 128 + r2]);
        float act = (q == 2) ? tanha(g2) : sigf(g2);
        float fv = __shfl_sync(0xffffffffu, act, lb | 1, 32);
        float gv = __shfl_sync(0xffffffffu, act, lb | 2, 32);
        float ov = __shfl_sync(0xffffffffu, act, lb | 3, 32);
        if (q == 0) {
            c2 = fv * c2 + act * gv;          // act = iv
            float h2n = ov * tanha(c2);
            h2s[j & 1][v] = h2n;
            g_hc2[j * 32 + v] = make_float2(h2n, c2);
        }
        __syncthreads();
    }
}

// ---------------- K6: batched forecast cells + both output heads ----------------
// grid 512, block 256
__global__ void post_kernel(const float* __restrict__ bih2,
                            const float* __restrict__ bhh2,
                            const float* __restrict__ Wfc8,
                            const float* __restrict__ bfc8,
                            float* __restrict__ out) {
    __shared__ float sh1[64], sh2[32], sfh1[64];
    __shared__ float sg[256], sg2[128];
    int t = threadIdx.x;
    int s = blockIdx.x;
    float c1v = 0.f, c2v = 0.f;
    if (t < 64) {
        float2 v = g_hc1[s * 64 + t];
        sh1[t] = v.x;
        c1v = v.y;
    }
    if (t < 32) {
        float2 v = g_hc2[s * 32 + t];
        sh2[t] = v.x;
        c2v = v.y;
    }
    __syncthreads();

    {
        float a = g_AF1[s * 256 + t];
#pragma unroll 8
        for (int k = 0; k < 64; k++)
            a += g_WT1[k * 256 + t] * sh1[k];
        sg[t] = a;
    }
    __syncthreads();
    if (t < 64) {
        float iv = sigf(sg[t]), fv = sigf(sg[64 + t]);
        float gv = tanha(sg[128 + t]), ov = sigf(sg[192 + t]);
        float cf = fv * c1v + iv * gv;
        sfh1[t] = ov * tanha(cf);
    }
    __syncthreads();

    if (t < 128) {
        float a = bih2[t] + bhh2[t];
#pragma unroll 8
        for (int k = 0; k < 64; k++)
            a += g_WTI2[k * 128 + t] * sfh1[k];
#pragma unroll 8
        for (int k = 0; k < 32; k++)
            a += g_WTH2[k * 128 + t] * sh2[k];
        sg2[t] = a;
    }
    __syncthreads();
    if (t < 32) {
        float iv = sigf(sg2[t]), fv = sigf(sg2[32 + t]);
        float gv = tanha(sg2[64 + t]), ov = sigf(sg2[96 + t]);
        float cf = fv * c2v + iv * gv;
        float fh2 = ov * tanha(cf);
        float w = Wfc8[t];
        float pd = w * sh2[t];
        float fd = w * fh2;
#pragma unroll
        for (int o = 16; o; o >>= 1) {
            pd += __shfl_down_sync(0xffffffffu, pd, o);
            fd += __shfl_down_sync(0xffffffffu, fd, o);
        }
        if (t == 0) {
            float b8 = bfc8[0];
            out[s] = sigf(pd + b8);
            out[512 + s] = sigf(fd + b8);
        }
    }
}

// ---------------- launch: prod || l1scan || (proj2+l2scan) — pure event edges -----------
extern "C" void kernel_launch(void* const* d_in, const int* in_sizes, int n_in,
                              void* d_out, int out_size) {
    const float* frames = (const float*)d_in[0];
    const float* W_spp  = (const float*)d_in[1];
    const float* b_spp  = (const float*)d_in[2];
    const float* W_fc7  = (const float*)d_in[3];
    const float* b_fc7  = (const float*)d_in[4];
    const float* W_fcast= (const float*)d_in[5];
    const float* b_fcast= (const float*)d_in[6];
    const float* Wih1   = (const float*)d_in[7];
    const float* Whh1   = (const float*)d_in[8];
    const float* bih1   = (const float*)d_in[9];
    const float* bhh1   = (const float*)d_in[10];
    const float* Wih2   = (const float*)d_in[11];
    const float* Whh2   = (const float*)d_in[12];
    const float* bih2   = (const float*)d_in[13];
    const float* bhh2   = (const float*)d_in[14];
    const float* W_fc8  = (const float*)d_in[15];
    const float* b_fc8  = (const float*)d_in[16];
    float* out = (float*)d_out;

    float *p_pooled, *p_X, *p_Ypart, *p_A1, *p_AF1;
    cudaGetSymbolAddress((void**)&p_pooled, g_pooled);
    cudaGetSymbolAddress((void**)&p_X, g_X);
    cudaGetSymbolAddress((void**)&p_Ypart, g_Ypart);
    cudaGetSymbolAddress((void**)&p_A1, g_A1);
    cudaGetSymbolAddress((void**)&p_AF1, g_AF1);

    // one-time handle creation (reused every call — identical launch pattern each time;
    // no new host/driver allocations during the capture call)
    static cudaStream_t s2 = nullptr, s3 = nullptr;
    static cudaEvent_t evP[4], evL1[4], evEnd;
    if (!s2) {
        cudaStreamCreateWithFlags(&s2, cudaStreamNonBlocking);
        cudaStreamCreateWithFlags(&s3, cudaStreamNonBlocking);
        for (int c = 0; c < 4; c++) {
            cudaEventCreateWithFlags(&evP[c], cudaEventDisableTiming);
            cudaEventCreateWithFlags(&evL1[c], cudaEventDisableTiming);
        }
        cudaEventCreateWithFlags(&evEnd, cudaEventDisableTiming);
    }

    for (int c = 0; c < 4; c++) {
        int sb = c * 128;
        // production chunk on the main (capturing) stream
        spp_kernel<<<384, 256>>>(frames, p_pooled, sb, Whh1, Wih1, Wih2, Whh2);
        gemm1_kernel<<<dim3(64, 4), 256>>>(p_pooled, W_spp, b_spp, p_X, sb);
        gemm2_kernel<<<dim3(32, 2), 256>>>(p_X, W_fc7, W_fcast, p_Ypart, sb);
        proj_kernel<<<128, 256>>>(p_Ypart, b_fc7, b_fcast, bih1, bhh1, p_A1, p_AF1, sb);
        cudaEventRecord(evP[c], 0);
        // L1-only sequential scan chunk on s2 (critical path)
        cudaStreamWaitEvent(s2, evP[c], 0);
        l1scan_kernel<<<1, 128, 0, s2>>>(Whh1, c);
        cudaEventRecord(evL1[c], s2);
        // cell2 pipeline on s3 (overlaps next chunk's l1scan)
        cudaStreamWaitEvent(s3, evL1[c], 0);
        proj2_kernel<<<128, 128, 0, s3>>>(bih2, bhh2, sb);
        l2scan_kernel<<<1, 128, 0, s3>>>(Whh2, c);
    }

    // post needs h1 (evL1 chain), h2/c2 (s3 order), AF1 (evP -> evL1 chain)
    post_kernel<<<512, 256, 0, s3>>>(bih2, bhh2, W_fc8, b_fc8, out);
    cudaEventRecord(evEnd, s3);
    cudaStreamWaitEvent(0, evEnd, 0);
}